// round 16
// baseline (speedup 1.0000x reference)
#include <cuda_runtime.h>
#include <cuda_bf16.h>
#include <cstdint>

#define N_NODES  100000
#define N_EDGES  1600000
#define IN_DIM   500
#define KPAD     512
#define HID      32
#define N_REL    7
#define OUT_DIM  4
#define N_GRAPHS 16
#define NCOL     256

// GEMM tiling (proven config: 116 us, regs=128, 2 CTA/SM)
#define BM 64
#define BN 256
#define BK 32
#define NITER (KPAD / BK)   // 16
#define PITCH 40            // smem row pitch in bf16 (80B): conflict-free for ldmatrix

// ---------------- scratch (device globals: allocation-free) ----------------
__device__ __nv_bfloat16 g_Hb[(size_t)N_NODES * NCOL]; // 51.2 MB
__device__ float g_O[(size_t)N_NODES * HID];           // 12.8 MB: direct node accum
__device__ float g_cnt[(size_t)N_NODES * N_REL];       // 2.8 MB: raw edge counts
__device__ float g_pool[N_GRAPHS * HID];
__device__ __nv_bfloat16 g_WT[NCOL * KPAD];            // W^T bf16 [n][k], zero-padded

// ---------------- prep: zero scratch + build bf16 W^T (fused) --------------
__global__ void prep_kernel(const float* __restrict__ W_rel,
                            const float* __restrict__ W_root) {
    int i = blockIdx.x * blockDim.x + threadIdx.x;
    if (i < N_NODES * HID / 4)  ((float4*)g_O)[i]   = make_float4(0.f, 0.f, 0.f, 0.f);
    if (i < N_NODES * N_REL / 4) ((float4*)g_cnt)[i] = make_float4(0.f, 0.f, 0.f, 0.f);
    if (i < N_GRAPHS * HID) g_pool[i] = 0.0f;
    if (i < NCOL * KPAD) {
        int n = i / KPAD;
        int k = i % KPAD;
        float w = 0.0f;
        if (k < IN_DIM) {
            if (n < HID) w = W_root[k * HID + n];
            else {
                int r = (n - HID) / HID;
                int j = n & (HID - 1);
                w = W_rel[((size_t)r * IN_DIM + k) * HID + j];
            }
        }
        g_WT[i] = __float2bfloat16(w);
    }
}

__global__ void count_kernel(const int* __restrict__ ei, const int* __restrict__ ea) {
    int e = blockIdx.x * blockDim.x + threadIdx.x;
    if (e >= N_EDGES) return;
    int dst = ei[N_EDGES + e];
    int r   = ea[e];
    if ((unsigned)dst >= N_NODES || (unsigned)r >= N_REL) return;
    atomicAdd(&g_cnt[(size_t)dst * N_REL + r], 1.0f);
}

// ---------------- tensor-core GEMM (2-stage smem, A regs 2-deep) ----------
__device__ __forceinline__ void mma_bf16(float* c, const uint32_t* a, const uint32_t* b) {
    asm volatile(
        "mma.sync.aligned.m16n8k16.row.col.f32.bf16.bf16.f32 "
        "{%0,%1,%2,%3}, {%4,%5,%6,%7}, {%8,%9}, {%0,%1,%2,%3};"
        : "+f"(c[0]), "+f"(c[1]), "+f"(c[2]), "+f"(c[3])
        : "r"(a[0]), "r"(a[1]), "r"(a[2]), "r"(a[3]), "r"(b[0]), "r"(b[1]));
}
__device__ __forceinline__ void ldm_x4(uint32_t* r, uint32_t addr) {
    asm volatile("ldmatrix.sync.aligned.m8n8.x4.shared.b16 {%0,%1,%2,%3}, [%4];"
                 : "=r"(r[0]), "=r"(r[1]), "=r"(r[2]), "=r"(r[3]) : "r"(addr));
}
__device__ __forceinline__ void cp_async16(uint32_t dst, const void* src) {
    asm volatile("cp.async.cg.shared.global [%0], [%1], 16;" :: "r"(dst), "l"(src));
}

// dynamic smem layout (bf16 elems): As[2][BM][PITCH] then Bs[2][BN][PITCH]
#define AS_ELEMS (BM * PITCH)          // 2560
#define BS_ELEMS (BN * PITCH)          // 10240
#define BS_BASE  (2 * AS_ELEMS)        // 5120
#define SMEM_BYTES ((2 * AS_ELEMS + 2 * BS_ELEMS) * 2)   // 51200

__global__ void __launch_bounds__(256, 2) gemm_kernel(const float* __restrict__ A) {
    extern __shared__ __nv_bfloat16 sm[];

    const int tid  = threadIdx.x;
    const int lane = tid & 31;
    const int wid  = tid >> 5;
    const int wm   = wid & 1;            // 2 warp rows x 32
    const int wn   = wid >> 1;           // 4 warp cols x 64
    const int bm   = blockIdx.x * BM;

    float acc[2][8][4];
    #pragma unroll
    for (int i = 0; i < 2; i++)
        #pragma unroll
        for (int j = 0; j < 8; j++)
            #pragma unroll
            for (int q = 0; q < 4; q++) acc[i][j][q] = 0.0f;

    const uint32_t sm_base = (uint32_t)__cvta_generic_to_shared(sm);
    const int ar0 = tid >> 3;
    const int ac4 = tid & 7;
    int gm0 = bm + ar0;      if (gm0 >= N_NODES) gm0 = N_NODES - 1;
    int gm1 = bm + ar0 + 32; if (gm1 >= N_NODES) gm1 = N_NODES - 1;
    const float* aptr0 = A + (size_t)gm0 * IN_DIM + ac4 * 4;
    const float* aptr1 = A + (size_t)gm1 * IN_DIM + ac4 * 4;
    const int bn_row = tid >> 2;
    const int bq     = tid & 3;
    const int a_row  = wm * 32 + (lane & 15);
    const int a_coff = (lane >> 4) * 16;
    const int b_row  = wn * 64 + (lane & 7) + ((lane & 16) >> 1);
    const int b_coff = ((lane >> 3) & 1) * 16;

    float4 abuf0[2], abuf1[2];

    auto issue_B = [&](int stage, int kt) {
        uint32_t dst = sm_base + (uint32_t)(BS_BASE + stage * BS_ELEMS) * 2;
        #pragma unroll
        for (int i = 0; i < 4; i++) {
            int n = bn_row + i * 64;
            cp_async16(dst + (uint32_t)(n * PITCH + bq * 8) * 2,
                       &g_WT[(size_t)n * KPAD + kt + bq * 8]);
        }
        asm volatile("cp.async.commit_group;");
    };
    auto issue_A = [&](int buf, int kt) {
        if (kt + ac4 * 4 + 3 < IN_DIM) {
            abuf0[buf] = *(const float4*)(aptr0 + kt);
            abuf1[buf] = *(const float4*)(aptr1 + kt);
        } else {
            const float* p0 = aptr0 + kt;
            const float* p1 = aptr1 + kt;
            int k0 = kt + ac4 * 4;
            float4 v0, v1;
            v0.x = (k0 + 0 < IN_DIM) ? p0[0] : 0.f;
            v0.y = (k0 + 1 < IN_DIM) ? p0[1] : 0.f;
            v0.z = (k0 + 2 < IN_DIM) ? p0[2] : 0.f;
            v0.w = (k0 + 3 < IN_DIM) ? p0[3] : 0.f;
            v1.x = (k0 + 0 < IN_DIM) ? p1[0] : 0.f;
            v1.y = (k0 + 1 < IN_DIM) ? p1[1] : 0.f;
            v1.z = (k0 + 2 < IN_DIM) ? p1[2] : 0.f;
            v1.w = (k0 + 3 < IN_DIM) ? p1[3] : 0.f;
            abuf0[buf] = v0; abuf1[buf] = v1;
        }
    };
    auto store_A = [&](int stage, int buf) {
        __nv_bfloat16* as = sm + stage * AS_ELEMS;
        float4 v0 = abuf0[buf], v1 = abuf1[buf];
        __nv_bfloat16 h0[4] = {__float2bfloat16(v0.x), __float2bfloat16(v0.y),
                               __float2bfloat16(v0.z), __float2bfloat16(v0.w)};
        __nv_bfloat16 h1[4] = {__float2bfloat16(v1.x), __float2bfloat16(v1.y),
                               __float2bfloat16(v1.z), __float2bfloat16(v1.w)};
        *(uint2*)&as[ar0 * PITCH + ac4 * 4]        = *(uint2*)h0;
        *(uint2*)&as[(ar0 + 32) * PITCH + ac4 * 4] = *(uint2*)h1;
    };

    issue_B(0, 0);
    issue_A(0, 0);
    store_A(0, 0);
    issue_A(1, BK);
    asm volatile("cp.async.wait_group 0;");
    __syncthreads();

    #pragma unroll
    for (int it = 0; it < NITER; it++) {
        const int cur = it & 1;
        const int nxt = cur ^ 1;
        if (it + 1 < NITER) {
            store_A(nxt, nxt);
            issue_B(nxt, (it + 1) * BK);
        }

        const uint32_t as_st = sm_base + (uint32_t)(cur * AS_ELEMS) * 2;
        const uint32_t bs_st = sm_base + (uint32_t)(BS_BASE + cur * BS_ELEMS) * 2;
        #pragma unroll
        for (int ks = 0; ks < 2; ks++) {
            const int kb = ks * 32;
            uint32_t ah[2][4];
            #pragma unroll
            for (int mi = 0; mi < 2; mi++)
                ldm_x4(ah[mi], as_st + (uint32_t)((a_row + mi * 16) * (PITCH * 2)) + kb + a_coff);
            uint32_t bh[4][4];
            #pragma unroll
            for (int bt = 0; bt < 4; bt++)
                ldm_x4(bh[bt], bs_st + (uint32_t)((b_row + bt * 16) * (PITCH * 2)) + kb + b_coff);
            #pragma unroll
            for (int mi = 0; mi < 2; mi++)
                #pragma unroll
                for (int ni = 0; ni < 8; ni++)
                    mma_bf16(acc[mi][ni], ah[mi], &bh[ni >> 1][(ni & 1) * 2]);
        }

        if (it + 2 < NITER) issue_A(cur, (it + 2) * BK);
        if (it + 1 < NITER) asm volatile("cp.async.wait_group 0;");
        __syncthreads();
    }

    #pragma unroll
    for (int mi = 0; mi < 2; mi++) {
        #pragma unroll
        for (int ni = 0; ni < 8; ni++) {
            int col = wn * 64 + ni * 8 + (lane & 3) * 2;
            int r0  = bm + wm * 32 + mi * 16 + (lane >> 2);
            __nv_bfloat162 v01 = __floats2bfloat162_rn(acc[mi][ni][0], acc[mi][ni][1]);
            __nv_bfloat162 v23 = __floats2bfloat162_rn(acc[mi][ni][2], acc[mi][ni][3]);
            if (r0 < N_NODES)
                *(__nv_bfloat162*)&g_Hb[(size_t)r0 * NCOL + col] = v01;
            if (r0 + 8 < N_NODES)
                *(__nv_bfloat162*)&g_Hb[(size_t)(r0 + 8) * NCOL + col] = v23;
        }
    }
}

// ---------------- edge scatter: O[dst,:] += H[src, rel slice] * rcp(cnt) ---
// 1 thread/edge: indices+cnt loaded ONCE (was 4x redundant), 2x uint4 gather,
// 8 REDG.v4. Halves L1tex instruction count on an LSU-bound kernel.
__global__ void __launch_bounds__(256) edge_kernel(const int* __restrict__ ei,
                                                   const int* __restrict__ ea) {
    int e = blockIdx.x * blockDim.x + threadIdx.x;
    if (e >= N_EDGES) return;
    int src = ei[e];
    int dst = ei[N_EDGES + e];
    int r   = ea[e];
    if ((unsigned)src >= N_NODES || (unsigned)dst >= N_NODES || (unsigned)r >= N_REL) return;
    float c   = __ldg(&g_cnt[(size_t)dst * N_REL + r]);
    float inv = __frcp_rn(fmaxf(c, 1.0f));
    const uint4* hp = (const uint4*)&g_Hb[(size_t)src * NCOL + (r + 1) * HID];
    uint4 h0 = hp[0];
    uint4 h1 = hp[1];
    float* op = &g_O[(size_t)dst * HID];

    float2 a0 = __bfloat1622float2(*(const __nv_bfloat162*)&h0.x);
    float2 a1 = __bfloat1622float2(*(const __nv_bfloat162*)&h0.y);
    float2 a2 = __bfloat1622float2(*(const __nv_bfloat162*)&h0.z);
    float2 a3 = __bfloat1622float2(*(const __nv_bfloat162*)&h0.w);
    asm volatile("red.global.add.v4.f32 [%0], {%1, %2, %3, %4};"
                 :: "l"(op), "f"(a0.x * inv), "f"(a0.y * inv),
                    "f"(a1.x * inv), "f"(a1.y * inv) : "memory");
    asm volatile("red.global.add.v4.f32 [%0], {%1, %2, %3, %4};"
                 :: "l"(op + 4), "f"(a2.x * inv), "f"(a2.y * inv),
                    "f"(a3.x * inv), "f"(a3.y * inv) : "memory");

    float2 b0 = __bfloat1622float2(*(const __nv_bfloat162*)&h1.x);
    float2 b1 = __bfloat1622float2(*(const __nv_bfloat162*)&h1.y);
    float2 b2 = __bfloat1622float2(*(const __nv_bfloat162*)&h1.z);
    float2 b3 = __bfloat1622float2(*(const __nv_bfloat162*)&h1.w);
    asm volatile("red.global.add.v4.f32 [%0], {%1, %2, %3, %4};"
                 :: "l"(op + 8), "f"(b0.x * inv), "f"(b0.y * inv),
                    "f"(b1.x * inv), "f"(b1.y * inv) : "memory");
    asm volatile("red.global.add.v4.f32 [%0], {%1, %2, %3, %4};"
                 :: "l"(op + 12), "f"(b2.x * inv), "f"(b2.y * inv),
                    "f"(b3.x * inv), "f"(b3.y * inv) : "memory");

    const uint4* hp2 = hp + 2;   // remaining 16 bf16 of the 32-wide slice
    uint4 h2 = hp2[0];
    uint4 h3 = hp2[1];
    float2 c0 = __bfloat1622float2(*(const __nv_bfloat162*)&h2.x);
    float2 c1 = __bfloat1622float2(*(const __nv_bfloat162*)&h2.y);
    float2 c2 = __bfloat1622float2(*(const __nv_bfloat162*)&h2.z);
    float2 c3 = __bfloat1622float2(*(const __nv_bfloat162*)&h2.w);
    asm volatile("red.global.add.v4.f32 [%0], {%1, %2, %3, %4};"
                 :: "l"(op + 16), "f"(c0.x * inv), "f"(c0.y * inv),
                    "f"(c1.x * inv), "f"(c1.y * inv) : "memory");
    asm volatile("red.global.add.v4.f32 [%0], {%1, %2, %3, %4};"
                 :: "l"(op + 20), "f"(c2.x * inv), "f"(c2.y * inv),
                    "f"(c3.x * inv), "f"(c3.y * inv) : "memory");
    float2 d0 = __bfloat1622float2(*(const __nv_bfloat162*)&h3.x);
    float2 d1 = __bfloat1622float2(*(const __nv_bfloat162*)&h3.y);
    float2 d2 = __bfloat1622float2(*(const __nv_bfloat162*)&h3.z);
    float2 d3 = __bfloat1622float2(*(const __nv_bfloat162*)&h3.w);
    asm volatile("red.global.add.v4.f32 [%0], {%1, %2, %3, %4};"
                 :: "l"(op + 24), "f"(d0.x * inv), "f"(d0.y * inv),
                    "f"(d1.x * inv), "f"(d1.y * inv) : "memory");
    asm volatile("red.global.add.v4.f32 [%0], {%1, %2, %3, %4};"
                 :: "l"(op + 28), "f"(d2.x * inv), "f"(d2.y * inv),
                    "f"(d3.x * inv), "f"(d3.y * inv) : "memory");
}

// ---------------- node combine + relu + pool -------------------------------
__global__ void __launch_bounds__(256) node_kernel(const int* __restrict__ batch,
                                                   const float* __restrict__ bias) {
    int n = blockIdx.x * 8 + (threadIdx.x >> 5);
    int j = threadIdx.x & 31;
    if (n >= N_NODES) return;
    float v = __bfloat162float(g_Hb[(size_t)n * NCOL + j]) + bias[j]
            + g_O[(size_t)n * HID + j];
    v = fmaxf(v, 0.0f);
    int g = batch[n];
    if ((unsigned)g >= N_GRAPHS) return;
    atomicAdd(&g_pool[g * HID + j], v);
}

// ---------------- final: out[16,4] = pool[16,32] @ fc_w[32,4] + fc_b -------
__global__ void final_kernel(const float* __restrict__ fc_w,
                             const float* __restrict__ fc_b,
                             float* __restrict__ out) {
    int t = threadIdx.x;
    if (t >= N_GRAPHS * OUT_DIM) return;
    int g = t / OUT_DIM, o = t % OUT_DIM;
    float s = fc_b[o];
    #pragma unroll
    for (int h = 0; h < HID; h++)
        s += g_pool[g * HID + h] * fc_w[h * OUT_DIM + o];
    out[t] = s;
}

// ---------------- launch ----------------------------------------------------
extern "C" void kernel_launch(void* const* d_in, const int* in_sizes, int n_in,
                              void* d_out, int out_size) {
    const float* node_x     = 0;  // 50,000,000
    const int*   edge_index = 0;  //  3,200,000
    const int*   edge_attr  = 0;  //  1,600,000
    const int*   batch      = 0;  //    100,000
    const float* W_rel      = 0;  //    112,000
    const float* W_root     = 0;  //     16,000
    const float* bias       = 0;  //         32
    const float* fc_w       = 0;  //        128
    const float* fc_b       = 0;  //          4

    for (int i = 0; i < n_in; i++) {
        switch (in_sizes[i]) {
            case 50000000: node_x     = (const float*)d_in[i]; break;
            case  3200000: edge_index = (const int*)d_in[i];   break;
            case  1600000: edge_attr  = (const int*)d_in[i];   break;
            case   100000: batch      = (const int*)d_in[i];   break;
            case   112000: W_rel      = (const float*)d_in[i]; break;
            case    16000: W_root     = (const float*)d_in[i]; break;
            case       32: bias       = (const float*)d_in[i]; break;
            case      128: fc_w       = (const float*)d_in[i]; break;
            case        4: fc_b       = (const float*)d_in[i]; break;
            default: break;
        }
    }
    float* out = (float*)d_out;

    static int init_done = 0;
    if (!init_done) {
        cudaFuncSetAttribute(gemm_kernel, cudaFuncAttributeMaxDynamicSharedMemorySize, SMEM_BYTES);
        init_done = 1;
    }

    // edge_kernel kept 4th so ncu's fixed skip profiles it again
    prep_kernel<<<(N_NODES * HID / 4 + 255) / 256, 256>>>(W_rel, W_root);
    count_kernel<<<(N_EDGES + 255) / 256, 256>>>(edge_index, edge_attr);
    gemm_kernel<<<(N_NODES + BM - 1) / BM, 256, SMEM_BYTES>>>(node_x);
    edge_kernel<<<(N_EDGES + 255) / 256, 256>>>(edge_index, edge_attr);
    node_kernel<<<N_NODES / 8, 256>>>(batch, bias);
    final_kernel<<<1, 64>>>(fc_w, fc_b, out);
}

// round 17
// speedup vs baseline: 1.5353x; 1.5353x over previous
#include <cuda_runtime.h>
#include <cuda_bf16.h>
#include <cstdint>

#define N_NODES  100000
#define N_EDGES  1600000
#define IN_DIM   500
#define KPAD     512
#define HID      32
#define N_REL    7
#define OUT_DIM  4
#define N_GRAPHS 16
#define NCOL     256

// GEMM tiling (proven config: 116 us, regs=128, 2 CTA/SM)
#define BM 64
#define BN 256
#define BK 32
#define NITER (KPAD / BK)   // 16
#define PITCH 40            // smem row pitch in bf16 (80B): conflict-free for ldmatrix

// node_kernel chunking
#define NCHUNK 16
#define NCHUNKS ((N_NODES + NCHUNK - 1) / NCHUNK)   // 6250

// ---------------- scratch (device globals: allocation-free) ----------------
__device__ __nv_bfloat16 g_Hb[(size_t)N_NODES * NCOL]; // 51.2 MB
__device__ float g_O[(size_t)N_NODES * HID];           // 12.8 MB: direct node accum
__device__ float g_cnt[(size_t)N_NODES * N_REL];       // 2.8 MB: raw edge counts
__device__ float g_pool[N_GRAPHS * HID];
__device__ __nv_bfloat16 g_WT[NCOL * KPAD];            // W^T bf16 [n][k], zero-padded

// ---------------- prep: zero scratch + build bf16 W^T (fused) --------------
__global__ void prep_kernel(const float* __restrict__ W_rel,
                            const float* __restrict__ W_root) {
    int i = blockIdx.x * blockDim.x + threadIdx.x;
    if (i < N_NODES * HID / 4)  ((float4*)g_O)[i]   = make_float4(0.f, 0.f, 0.f, 0.f);
    if (i < N_NODES * N_REL / 4) ((float4*)g_cnt)[i] = make_float4(0.f, 0.f, 0.f, 0.f);
    if (i < N_GRAPHS * HID) g_pool[i] = 0.0f;
    if (i < NCOL * KPAD) {
        int n = i / KPAD;
        int k = i % KPAD;
        float w = 0.0f;
        if (k < IN_DIM) {
            if (n < HID) w = W_root[k * HID + n];
            else {
                int r = (n - HID) / HID;
                int j = n & (HID - 1);
                w = W_rel[((size_t)r * IN_DIM + k) * HID + j];
            }
        }
        g_WT[i] = __float2bfloat16(w);
    }
}

__global__ void count_kernel(const int* __restrict__ ei, const int* __restrict__ ea) {
    int e = blockIdx.x * blockDim.x + threadIdx.x;
    if (e >= N_EDGES) return;
    int dst = ei[N_EDGES + e];
    int r   = ea[e];
    if ((unsigned)dst >= N_NODES || (unsigned)r >= N_REL) return;
    atomicAdd(&g_cnt[(size_t)dst * N_REL + r], 1.0f);
}

// ---------------- tensor-core GEMM (2-stage smem, A regs 2-deep) ----------
__device__ __forceinline__ void mma_bf16(float* c, const uint32_t* a, const uint32_t* b) {
    asm volatile(
        "mma.sync.aligned.m16n8k16.row.col.f32.bf16.bf16.f32 "
        "{%0,%1,%2,%3}, {%4,%5,%6,%7}, {%8,%9}, {%0,%1,%2,%3};"
        : "+f"(c[0]), "+f"(c[1]), "+f"(c[2]), "+f"(c[3])
        : "r"(a[0]), "r"(a[1]), "r"(a[2]), "r"(a[3]), "r"(b[0]), "r"(b[1]));
}
__device__ __forceinline__ void ldm_x4(uint32_t* r, uint32_t addr) {
    asm volatile("ldmatrix.sync.aligned.m8n8.x4.shared.b16 {%0,%1,%2,%3}, [%4];"
                 : "=r"(r[0]), "=r"(r[1]), "=r"(r[2]), "=r"(r[3]) : "r"(addr));
}
__device__ __forceinline__ void cp_async16(uint32_t dst, const void* src) {
    asm volatile("cp.async.cg.shared.global [%0], [%1], 16;" :: "r"(dst), "l"(src));
}

// dynamic smem layout (bf16 elems): As[2][BM][PITCH] then Bs[2][BN][PITCH]
#define AS_ELEMS (BM * PITCH)          // 2560
#define BS_ELEMS (BN * PITCH)          // 10240
#define BS_BASE  (2 * AS_ELEMS)        // 5120
#define SMEM_BYTES ((2 * AS_ELEMS + 2 * BS_ELEMS) * 2)   // 51200

__global__ void __launch_bounds__(256, 2) gemm_kernel(const float* __restrict__ A) {
    extern __shared__ __nv_bfloat16 sm[];

    const int tid  = threadIdx.x;
    const int lane = tid & 31;
    const int wid  = tid >> 5;
    const int wm   = wid & 1;            // 2 warp rows x 32
    const int wn   = wid >> 1;           // 4 warp cols x 64
    const int bm   = blockIdx.x * BM;

    float acc[2][8][4];
    #pragma unroll
    for (int i = 0; i < 2; i++)
        #pragma unroll
        for (int j = 0; j < 8; j++)
            #pragma unroll
            for (int q = 0; q < 4; q++) acc[i][j][q] = 0.0f;

    const uint32_t sm_base = (uint32_t)__cvta_generic_to_shared(sm);
    const int ar0 = tid >> 3;
    const int ac4 = tid & 7;
    int gm0 = bm + ar0;      if (gm0 >= N_NODES) gm0 = N_NODES - 1;
    int gm1 = bm + ar0 + 32; if (gm1 >= N_NODES) gm1 = N_NODES - 1;
    const float* aptr0 = A + (size_t)gm0 * IN_DIM + ac4 * 4;
    const float* aptr1 = A + (size_t)gm1 * IN_DIM + ac4 * 4;
    const int bn_row = tid >> 2;
    const int bq     = tid & 3;
    const int a_row  = wm * 32 + (lane & 15);
    const int a_coff = (lane >> 4) * 16;
    const int b_row  = wn * 64 + (lane & 7) + ((lane & 16) >> 1);
    const int b_coff = ((lane >> 3) & 1) * 16;

    float4 abuf0[2], abuf1[2];

    auto issue_B = [&](int stage, int kt) {
        uint32_t dst = sm_base + (uint32_t)(BS_BASE + stage * BS_ELEMS) * 2;
        #pragma unroll
        for (int i = 0; i < 4; i++) {
            int n = bn_row + i * 64;
            cp_async16(dst + (uint32_t)(n * PITCH + bq * 8) * 2,
                       &g_WT[(size_t)n * KPAD + kt + bq * 8]);
        }
        asm volatile("cp.async.commit_group;");
    };
    auto issue_A = [&](int buf, int kt) {
        if (kt + ac4 * 4 + 3 < IN_DIM) {
            abuf0[buf] = *(const float4*)(aptr0 + kt);
            abuf1[buf] = *(const float4*)(aptr1 + kt);
        } else {
            const float* p0 = aptr0 + kt;
            const float* p1 = aptr1 + kt;
            int k0 = kt + ac4 * 4;
            float4 v0, v1;
            v0.x = (k0 + 0 < IN_DIM) ? p0[0] : 0.f;
            v0.y = (k0 + 1 < IN_DIM) ? p0[1] : 0.f;
            v0.z = (k0 + 2 < IN_DIM) ? p0[2] : 0.f;
            v0.w = (k0 + 3 < IN_DIM) ? p0[3] : 0.f;
            v1.x = (k0 + 0 < IN_DIM) ? p1[0] : 0.f;
            v1.y = (k0 + 1 < IN_DIM) ? p1[1] : 0.f;
            v1.z = (k0 + 2 < IN_DIM) ? p1[2] : 0.f;
            v1.w = (k0 + 3 < IN_DIM) ? p1[3] : 0.f;
            abuf0[buf] = v0; abuf1[buf] = v1;
        }
    };
    auto store_A = [&](int stage, int buf) {
        __nv_bfloat16* as = sm + stage * AS_ELEMS;
        float4 v0 = abuf0[buf], v1 = abuf1[buf];
        __nv_bfloat16 h0[4] = {__float2bfloat16(v0.x), __float2bfloat16(v0.y),
                               __float2bfloat16(v0.z), __float2bfloat16(v0.w)};
        __nv_bfloat16 h1[4] = {__float2bfloat16(v1.x), __float2bfloat16(v1.y),
                               __float2bfloat16(v1.z), __float2bfloat16(v1.w)};
        *(uint2*)&as[ar0 * PITCH + ac4 * 4]        = *(uint2*)h0;
        *(uint2*)&as[(ar0 + 32) * PITCH + ac4 * 4] = *(uint2*)h1;
    };

    issue_B(0, 0);
    issue_A(0, 0);
    store_A(0, 0);
    issue_A(1, BK);
    asm volatile("cp.async.wait_group 0;");
    __syncthreads();

    #pragma unroll
    for (int it = 0; it < NITER; it++) {
        const int cur = it & 1;
        const int nxt = cur ^ 1;
        if (it + 1 < NITER) {
            store_A(nxt, nxt);
            issue_B(nxt, (it + 1) * BK);
        }

        const uint32_t as_st = sm_base + (uint32_t)(cur * AS_ELEMS) * 2;
        const uint32_t bs_st = sm_base + (uint32_t)(BS_BASE + cur * BS_ELEMS) * 2;
        #pragma unroll
        for (int ks = 0; ks < 2; ks++) {
            const int kb = ks * 32;
            uint32_t ah[2][4];
            #pragma unroll
            for (int mi = 0; mi < 2; mi++)
                ldm_x4(ah[mi], as_st + (uint32_t)((a_row + mi * 16) * (PITCH * 2)) + kb + a_coff);
            uint32_t bh[4][4];
            #pragma unroll
            for (int bt = 0; bt < 4; bt++)
                ldm_x4(bh[bt], bs_st + (uint32_t)((b_row + bt * 16) * (PITCH * 2)) + kb + b_coff);
            #pragma unroll
            for (int mi = 0; mi < 2; mi++)
                #pragma unroll
                for (int ni = 0; ni < 8; ni++)
                    mma_bf16(acc[mi][ni], ah[mi], &bh[ni >> 1][(ni & 1) * 2]);
        }

        if (it + 2 < NITER) issue_A(cur, (it + 2) * BK);
        if (it + 1 < NITER) asm volatile("cp.async.wait_group 0;");
        __syncthreads();
    }

    #pragma unroll
    for (int mi = 0; mi < 2; mi++) {
        #pragma unroll
        for (int ni = 0; ni < 8; ni++) {
            int col = wn * 64 + ni * 8 + (lane & 3) * 2;
            int r0  = bm + wm * 32 + mi * 16 + (lane >> 2);
            __nv_bfloat162 v01 = __floats2bfloat162_rn(acc[mi][ni][0], acc[mi][ni][1]);
            __nv_bfloat162 v23 = __floats2bfloat162_rn(acc[mi][ni][2], acc[mi][ni][3]);
            if (r0 < N_NODES)
                *(__nv_bfloat162*)&g_Hb[(size_t)r0 * NCOL + col] = v01;
            if (r0 + 8 < N_NODES)
                *(__nv_bfloat162*)&g_Hb[(size_t)(r0 + 8) * NCOL + col] = v23;
        }
    }
}

// ---------------- edge scatter: O[dst,:] += H[src, rel slice] * rcp(cnt) ---
// 4 threads/edge (R15 proven layout: intra-edge coalescing is load-bearing)
__global__ void __launch_bounds__(256) edge_kernel(const int* __restrict__ ei,
                                                   const int* __restrict__ ea) {
    int t = blockIdx.x * blockDim.x + threadIdx.x;
    int e = t >> 2;
    int l = t & 3;
    if (e >= N_EDGES) return;
    int src = ei[e];
    int dst = ei[N_EDGES + e];
    int r   = ea[e];
    if ((unsigned)src >= N_NODES || (unsigned)dst >= N_NODES || (unsigned)r >= N_REL) return;
    float c   = __ldg(&g_cnt[(size_t)dst * N_REL + r]);
    float inv = __frcp_rn(fmaxf(c, 1.0f));
    const uint4 h = *(const uint4*)&g_Hb[(size_t)src * NCOL + (r + 1) * HID + l * 8];
    float2 f0 = __bfloat1622float2(*(const __nv_bfloat162*)&h.x);
    float2 f1 = __bfloat1622float2(*(const __nv_bfloat162*)&h.y);
    float2 f2 = __bfloat1622float2(*(const __nv_bfloat162*)&h.z);
    float2 f3 = __bfloat1622float2(*(const __nv_bfloat162*)&h.w);
    float* op = &g_O[(size_t)dst * HID + l * 8];
    asm volatile("red.global.add.v4.f32 [%0], {%1, %2, %3, %4};"
                 :: "l"(op), "f"(f0.x * inv), "f"(f0.y * inv),
                    "f"(f1.x * inv), "f"(f1.y * inv) : "memory");
    asm volatile("red.global.add.v4.f32 [%0], {%1, %2, %3, %4};"
                 :: "l"(op + 4), "f"(f2.x * inv), "f"(f2.y * inv),
                    "f"(f3.x * inv), "f"(f3.y * inv) : "memory");
}

// ---------------- node combine + relu + run-length pooled reduction --------
// Thread owns channel j for NCHUNK consecutive nodes; batch is SORTED, so
// per-graph partials accumulate in registers and flush once per transition:
// pool atomics drop from 3.2M to ~210K.
__global__ void __launch_bounds__(256) node_kernel(const int* __restrict__ batch,
                                                   const float* __restrict__ bias) {
    int t = blockIdx.x * blockDim.x + threadIdx.x;
    int chunk = t >> 5;
    int j = t & 31;
    if (chunk >= NCHUNKS) return;
    int n0 = chunk * NCHUNK;
    int n1 = (n0 + NCHUNK < N_NODES) ? n0 + NCHUNK : N_NODES;
    float bj = bias[j];
    float acc = 0.0f;
    int gcur = batch[n0];
    for (int n = n0; n < n1; n++) {
        float v = __bfloat162float(g_Hb[(size_t)n * NCOL + j]) + bj
                + g_O[(size_t)n * HID + j];
        v = fmaxf(v, 0.0f);
        int g = batch[n];
        if (g != gcur) {
            if ((unsigned)gcur < N_GRAPHS) atomicAdd(&g_pool[gcur * HID + j], acc);
            acc = 0.0f;
            gcur = g;
        }
        acc += v;
    }
    if ((unsigned)gcur < N_GRAPHS) atomicAdd(&g_pool[gcur * HID + j], acc);
}

// ---------------- final: out[16,4] = pool[16,32] @ fc_w[32,4] + fc_b -------
__global__ void final_kernel(const float* __restrict__ fc_w,
                             const float* __restrict__ fc_b,
                             float* __restrict__ out) {
    int t = threadIdx.x;
    if (t >= N_GRAPHS * OUT_DIM) return;
    int g = t / OUT_DIM, o = t % OUT_DIM;
    float s = fc_b[o];
    #pragma unroll
    for (int h = 0; h < HID; h++)
        s += g_pool[g * HID + h] * fc_w[h * OUT_DIM + o];
    out[t] = s;
}

// ---------------- launch ----------------------------------------------------
extern "C" void kernel_launch(void* const* d_in, const int* in_sizes, int n_in,
                              void* d_out, int out_size) {
    const float* node_x     = 0;  // 50,000,000
    const int*   edge_index = 0;  //  3,200,000
    const int*   edge_attr  = 0;  //  1,600,000
    const int*   batch      = 0;  //    100,000
    const float* W_rel      = 0;  //    112,000
    const float* W_root     = 0;  //     16,000
    const float* bias       = 0;  //         32
    const float* fc_w       = 0;  //        128
    const float* fc_b       = 0;  //          4

    for (int i = 0; i < n_in; i++) {
        switch (in_sizes[i]) {
            case 50000000: node_x     = (const float*)d_in[i]; break;
            case  3200000: edge_index = (const int*)d_in[i];   break;
            case  1600000: edge_attr  = (const int*)d_in[i];   break;
            case   100000: batch      = (const int*)d_in[i];   break;
            case   112000: W_rel      = (const float*)d_in[i]; break;
            case    16000: W_root     = (const float*)d_in[i]; break;
            case       32: bias       = (const float*)d_in[i]; break;
            case      128: fc_w       = (const float*)d_in[i]; break;
            case        4: fc_b       = (const float*)d_in[i]; break;
            default: break;
        }
    }
    float* out = (float*)d_out;

    static int init_done = 0;
    if (!init_done) {
        cudaFuncSetAttribute(gemm_kernel, cudaFuncAttributeMaxDynamicSharedMemorySize, SMEM_BYTES);
        init_done = 1;
    }

    prep_kernel<<<(N_NODES * HID / 4 + 255) / 256, 256>>>(W_rel, W_root);
    count_kernel<<<(N_EDGES + 255) / 256, 256>>>(edge_index, edge_attr);
    gemm_kernel<<<(N_NODES + BM - 1) / BM, 256, SMEM_BYTES>>>(node_x);
    edge_kernel<<<(N_EDGES * 4 + 255) / 256, 256>>>(edge_index, edge_attr);
    node_kernel<<<(NCHUNKS * 32 + 255) / 256, 256>>>(batch, bias);
    final_kernel<<<1, 64>>>(fc_w, fc_b, out);
}